// round 14
// baseline (speedup 1.0000x reference)
#include <cuda_runtime.h>
#include <cuda_bf16.h>
#include <cstdint>

// Round 14: time-split GEMM. Prologue kernel (all 148 SMs) precomputes pre for
// steps [0, S_PRE); combined kernel = 20 producer CTAs (chunks S_PRE/64..31)
// + 128 scan CTAs (round-7 scan, seen initialized to S_PRE).

#define BB 256
#define SS 2048
#define II 64
#define HH 128
#define GG 512
#define NPROD 20
#define NSCAN 128
#define NTHR 256
#define CHUNK 64
#define S_PRE 768                       // 12 chunks precomputed by prologue
#define PRE_TPB (S_PRE / 64)            // prologue tiles per batch row

#define REG_K 96
#define SMK   32
#define PTS  (SMK * 2 + 4)
#define SW_FLOATS (NTHR * PTS)
#define HB_FLOATS (2 * 2 * HH)

#define ARS 36
#define OFF_AH 0
#define OFF_AL (64 * ARS)
#define OFF_BH (2 * 64 * ARS)
#define OFF_BL (OFF_BH + 512 * ARS)
#define PROD_UINTS (OFF_BL + 512 * ARS)
#define SMEM_BYTES (PROD_UINTS * 4)

typedef unsigned long long u64;

__device__ float g_pre[(long long)BB * SS * GG];          // 1 GB scratch
__device__ __align__(16) unsigned g_wh[GG * II / 2];
__device__ __align__(16) unsigned g_wl[GG * II / 2];
__device__ volatile int g_flag[NSCAN];

__device__ __forceinline__ u64 ffma2(u64 a, u64 b, u64 c) {
    u64 d;
    asm("fma.rn.f32x2 %0, %1, %2, %3;" : "=l"(d) : "l"(a), "l"(b), "l"(c));
    return d;
}
__device__ __forceinline__ u64 packf2(float lo, float hi) {
    u64 r;
    asm("mov.b64 %0, {%1, %2};" : "=l"(r) : "f"(lo), "f"(hi));
    return r;
}
__device__ __forceinline__ float2 unpackf2(u64 v) {
    float2 r;
    asm("mov.b64 {%0, %1}, %2;" : "=f"(r.x), "=f"(r.y) : "l"(v));
    return r;
}
__device__ __forceinline__ float fast_tanh(float x) {
    float xc = fminf(fmaxf(x, -12.0f), 12.0f);
    float e  = __expf(2.0f * xc);
    return __fdividef(e - 1.0f, e + 1.0f);
}
__device__ __forceinline__ unsigned pack_bf16_hi(float a, float b) {
    __nv_bfloat16 ah = __float2bfloat16(a), bh = __float2bfloat16(b);
    return (unsigned)__bfloat16_as_ushort(ah) | ((unsigned)__bfloat16_as_ushort(bh) << 16);
}
__device__ __forceinline__ unsigned pack_bf16_lo(float a, float b) {
    __nv_bfloat16 ah = __float2bfloat16(a), bh = __float2bfloat16(b);
    __nv_bfloat16 al = __float2bfloat16(a - __bfloat162float(ah));
    __nv_bfloat16 bl = __float2bfloat16(b - __bfloat162float(bh));
    return (unsigned)__bfloat16_as_ushort(al) | ((unsigned)__bfloat16_as_ushort(bl) << 16);
}
__device__ __forceinline__ void mma16816(float* c, const unsigned* a,
                                         unsigned b0, unsigned b1) {
    asm volatile(
        "mma.sync.aligned.m16n8k16.row.col.f32.bf16.bf16.f32 "
        "{%0,%1,%2,%3}, {%4,%5,%6,%7}, {%8,%9}, {%0,%1,%2,%3};"
        : "+f"(c[0]), "+f"(c[1]), "+f"(c[2]), "+f"(c[3])
        : "r"(a[0]), "r"(a[1]), "r"(a[2]), "r"(a[3]), "r"(b0), "r"(b1));
}

__global__ void prep_w_kernel(const float* __restrict__ Wm) {
    int i = blockIdx.x * 256 + threadIdx.x;
    float a = Wm[2 * i], b = Wm[2 * i + 1];
    g_wh[i] = pack_bf16_hi(a, b);
    g_wl[i] = pack_bf16_lo(a, b);
    if (blockIdx.x == 0 && threadIdx.x < NSCAN) g_flag[threadIdx.x] = 0;
}

// shared B loader (full W bf16 hi/lo into smem)
__device__ __forceinline__ void load_B(unsigned* usm) {
    unsigned* Bh = usm + OFF_BH;
    unsigned* Bl = usm + OFF_BL;
    const int tid = threadIdx.x;
#pragma unroll
    for (int j = 0; j < 16; j++) {
        int idx = tid + j * 256;
        int n = idx >> 3, kq = idx & 7;
        uint4 hv = ((const uint4*)g_wh)[idx];
        uint4 lv = ((const uint4*)g_wl)[idx];
        *(uint4*)(Bh + n * ARS + kq * 4) = hv;
        *(uint4*)(Bl + n * ARS + kq * 4) = lv;
    }
}

// Producer tile: M=64 rows (mbase.. of flattened b*SS+s), N=512, K=64
__device__ void prod_tile(unsigned* usm, const float* __restrict__ xg,
                          float* pre, long long mbase) {
    unsigned* Ah = usm + OFF_AH;
    unsigned* Al = usm + OFF_AL;
    unsigned* Bh = usm + OFF_BH;
    unsigned* Bl = usm + OFF_BL;
    const int tid = threadIdx.x;

    __syncthreads();
    {
        const float* xt = xg + mbase * II;
#pragma unroll
        for (int j = 0; j < 8; j++) {
            int idx = tid + j * 256;
            int row = idx >> 5, kp = idx & 31;
            float2 v = *(const float2*)(xt + row * II + kp * 2);
            Ah[row * ARS + kp] = pack_bf16_hi(v.x, v.y);
            Al[row * ARS + kp] = pack_bf16_lo(v.x, v.y);
        }
    }
    __syncthreads();

    const int w    = tid >> 5;
    const int lane = tid & 31;
    const int gid  = lane >> 2;
    const int tig  = lane & 3;
    const int mg   = w >> 2;
    const int ng   = w & 3;

    float acc[2][16][4];
#pragma unroll
    for (int mt = 0; mt < 2; mt++)
#pragma unroll
        for (int nc = 0; nc < 16; nc++)
#pragma unroll
            for (int e = 0; e < 4; e++) acc[mt][nc][e] = 0.0f;

#pragma unroll
    for (int ks = 0; ks < 4; ks++) {
        unsigned ah[2][4], al[2][4];
#pragma unroll
        for (int mt = 0; mt < 2; mt++) {
            int r0 = mg * 32 + mt * 16 + gid;
            int ui = ks * 8 + tig;
            ah[mt][0] = Ah[r0 * ARS + ui];
            ah[mt][1] = Ah[(r0 + 8) * ARS + ui];
            ah[mt][2] = Ah[r0 * ARS + ui + 4];
            ah[mt][3] = Ah[(r0 + 8) * ARS + ui + 4];
            al[mt][0] = Al[r0 * ARS + ui];
            al[mt][1] = Al[(r0 + 8) * ARS + ui];
            al[mt][2] = Al[r0 * ARS + ui + 4];
            al[mt][3] = Al[(r0 + 8) * ARS + ui + 4];
        }
#pragma unroll
        for (int nc = 0; nc < 16; nc++) {
            int n  = ng * 128 + nc * 8 + gid;
            int ui = ks * 8 + tig;
            unsigned bh0 = Bh[n * ARS + ui];
            unsigned bh1 = Bh[n * ARS + ui + 4];
            unsigned bl0 = Bl[n * ARS + ui];
            unsigned bl1 = Bl[n * ARS + ui + 4];
#pragma unroll
            for (int mt = 0; mt < 2; mt++) {
                mma16816(acc[mt][nc], ah[mt], bh0, bh1);
                mma16816(acc[mt][nc], al[mt], bh0, bh1);
                mma16816(acc[mt][nc], ah[mt], bl0, bl1);
            }
        }
    }
#pragma unroll
    for (int mt = 0; mt < 2; mt++) {
#pragma unroll
        for (int nc = 0; nc < 16; nc++) {
            long long m = mbase + mg * 32 + mt * 16 + gid;
            int n = ng * 128 + nc * 8 + tig * 2;
            *(float2*)(pre + m * GG + n)       = make_float2(acc[mt][nc][0], acc[mt][nc][1]);
            *(float2*)(pre + (m + 8) * GG + n) = make_float2(acc[mt][nc][2], acc[mt][nc][3]);
        }
    }
}

// prologue GEMM: pre for steps [0, S_PRE) of all batch rows; all SMs.
__global__ void __launch_bounds__(NTHR, 1)
pre_gemm_prologue(const float* __restrict__ xg, float* pre)
{
    extern __shared__ float smemf[];
    unsigned* usm = (unsigned*)smemf;
    load_B(usm);
    int b = blockIdx.x / PRE_TPB;
    int t = blockIdx.x % PRE_TPB;
    prod_tile(usm, xg, pre, (long long)b * SS + (long long)t * 64);
}

// ---------------------------------------------------------------------------
__global__ void __launch_bounds__(NTHR, 1)
slstm_combined_kernel(const float* __restrict__ xg, const float* __restrict__ Rm,
                      const float* __restrict__ bias, float* pre,
                      float* __restrict__ out)
{
    extern __shared__ float smem[];
    const int tid = threadIdx.x;

    if (blockIdx.x < NPROD) {
        // ================= producer CTA: chunks [S_PRE/CHUNK, SS/CHUNK) ====
        unsigned* usm = (unsigned*)smem;
        load_B(usm);
        for (int chunk = S_PRE / CHUNK; chunk < SS / CHUNK; chunk++) {
            for (int pair = blockIdx.x; pair < NSCAN; pair += NPROD) {
                long long s0 = (long long)chunk * CHUNK;
                prod_tile(usm, xg, pre, (long long)(2 * pair)     * SS + s0);
                prod_tile(usm, xg, pre, (long long)(2 * pair + 1) * SS + s0);
                __syncthreads();
                if (tid == 0) {
                    __threadfence();
                    g_flag[pair] = (chunk + 1) * CHUNK;
                }
            }
        }
        return;
    }

    // ================= scan CTA (round-7 body) =================
    float* sW = smem;                    // [256][PTS]
    float* hb = smem + SW_FLOATS;        // [2][2][HH]

    const int pair = blockIdx.x - NPROD;
    const int b0   = pair * 2;
    const int w  = tid >> 5;
    const int l  = tid & 31;
    const int c0 = 16 * l + 2 * w;
    const int c1 = c0 + 1;

    u64 wp0[REG_K / 2], wp1[REG_K / 2];
#pragma unroll
    for (int j = 0; j < REG_K / 2; j++) {
        wp0[j] = packf2(Rm[(2 * j) * GG + c0], Rm[(2 * j + 1) * GG + c0]);
        wp1[j] = packf2(Rm[(2 * j) * GG + c1], Rm[(2 * j + 1) * GG + c1]);
    }
    {
        float* slab = sW + tid * PTS;
#pragma unroll
        for (int kc = 0; kc < SMK; kc += 4) {
            int k = REG_K + kc;
            slab[kc * 2 + 0] = Rm[(k + 0) * GG + c0];
            slab[kc * 2 + 1] = Rm[(k + 1) * GG + c0];
            slab[kc * 2 + 2] = Rm[(k + 0) * GG + c1];
            slab[kc * 2 + 3] = Rm[(k + 1) * GG + c1];
            slab[kc * 2 + 4] = Rm[(k + 2) * GG + c0];
            slab[kc * 2 + 5] = Rm[(k + 3) * GG + c0];
            slab[kc * 2 + 6] = Rm[(k + 2) * GG + c1];
            slab[kc * 2 + 7] = Rm[(k + 3) * GG + c1];
        }
    }
    const float bg0 = bias[c0];
    const float bg1 = bias[c1];

    hb[tid] = 0.0f;
    hb[tid + 256] = 0.0f;
    __syncthreads();

    const float* pr0 = pre + (long long)(b0)     * SS * GG;
    const float* pr1 = pre + (long long)(b0 + 1) * SS * GG;

    int seen = S_PRE;                    // prologue guarantees [0, S_PRE)
#define WAITS(need) do { int _n = (need); if (seen < _n) {                      \
        while ((seen = g_flag[pair]) < _n) {}                                   \
        __threadfence(); } } while (0)

    float2 p0 = *(const float2*)(pr0 + c0);
    float2 p1 = *(const float2*)(pr1 + c0);

    const int my_row = (l >> 4) & 1;
    const int my_hid = 16 * (l & 7) + 2 * w + ((l >> 3) & 1);
    float c_ = 0.0f, n_ = 0.0f, m_ = 0.0f;

    const bool lo16 = (l < 16);
    const bool b3   = ((l >> 3) & 1) != 0;
    const float* sWg = sW + tid * PTS;

#pragma unroll 1
    for (int step = 0; step < SS; step++) {
        const float* h0 = hb + (step & 1) * 256;
        const float* h1 = h0 + HH;
        float* hn = hb + ((step + 1) & 1) * 256;

        float2 q0 = make_float2(0.f, 0.f), q1 = make_float2(0.f, 0.f);
        if (step + 1 < SS) {
            WAITS(step + 2);
            long long off = (long long)(step + 1) * GG;
            q0 = *(const float2*)(pr0 + off + c0);
            q1 = *(const float2*)(pr1 + off + c0);
        }

        u64 a00 = 0, a10 = 0, a01 = 0, a11 = 0;

#pragma unroll
        for (int k = 0; k < REG_K; k += 4) {
            ulonglong2 hp0 = *(const ulonglong2*)(h0 + k);
            ulonglong2 hp1 = *(const ulonglong2*)(h1 + k);
            int j = k / 2;
            a00 = ffma2(hp0.x, wp0[j],     a00);
            a10 = ffma2(hp0.x, wp1[j],     a10);
            a01 = ffma2(hp1.x, wp0[j],     a01);
            a11 = ffma2(hp1.x, wp1[j],     a11);
            a00 = ffma2(hp0.y, wp0[j + 1], a00);
            a10 = ffma2(hp0.y, wp1[j + 1], a10);
            a01 = ffma2(hp1.y, wp0[j + 1], a01);
            a11 = ffma2(hp1.y, wp1[j + 1], a11);
        }
#pragma unroll
        for (int k = 0; k < SMK; k += 4) {
            ulonglong2 wv0 = *(const ulonglong2*)(sWg + k * 2);
            ulonglong2 wv1 = *(const ulonglong2*)(sWg + k * 2 + 4);
            ulonglong2 hp0 = *(const ulonglong2*)(h0 + REG_K + k);
            ulonglong2 hp1 = *(const ulonglong2*)(h1 + REG_K + k);
            a00 = ffma2(hp0.x, wv0.x, a00);
            a10 = ffma2(hp0.x, wv0.y, a10);
            a01 = ffma2(hp1.x, wv0.x, a01);
            a11 = ffma2(hp1.x, wv0.y, a11);
            a00 = ffma2(hp0.y, wv1.x, a00);
            a10 = ffma2(hp0.y, wv1.y, a10);
            a01 = ffma2(hp1.y, wv1.x, a01);
            a11 = ffma2(hp1.y, wv1.y, a11);
        }

        float2 t0 = unpackf2(a00), t1 = unpackf2(a10);
        float2 t2 = unpackf2(a01), t3 = unpackf2(a11);
        float aa = t0.x + t0.y + p0.x + bg0;
        float bb = t1.x + t1.y + p0.y + bg1;
        float cc = t2.x + t2.y + p1.x + bg0;
        float dd = t3.x + t3.y + p1.y + bg1;

        // warp-local gate transpose (4 shuffles)
        float u1 = lo16 ? cc : aa;
        float u2 = lo16 ? dd : bb;
        float r1v = __shfl_xor_sync(0xFFFFFFFFu, u1, 16);
        float r2v = __shfl_xor_sync(0xFFFFFFFFu, u2, 16);
        float Ag = lo16 ? aa : r1v;
        float Bg = lo16 ? bb : r2v;
        float Cg = lo16 ? r1v : cc;
        float Dg = lo16 ? r2v : dd;
        float s1in = b3 ? Ag : Bg;
        float s2in = b3 ? Cg : Dg;
        float e1 = __shfl_xor_sync(0xFFFFFFFFu, s1in, 8);
        float e2 = __shfl_xor_sync(0xFFFFFFFFu, s2in, 8);
        float iv = b3 ? e1 : Ag;
        float fv = b3 ? Bg : e1;
        float ov = b3 ? e2 : Cg;
        float zv = b3 ? Dg : e2;

        float tz = fast_tanh(zv);
        float so = __fdividef(1.0f, 1.0f + __expf(-ov));
        float lf = fminf(fv, 0.0f) - __logf(1.0f + __expf(-fabsf(fv)));
        float mn = fmaxf(lf + m_, iv);
        float ip = __expf(iv - mn);
        float fp = __expf(lf + m_ - mn);
        c_ = fp * c_ + ip * tz;
        n_ = fp * n_ + ip;
        m_ = mn;
        float hv = so * fast_tanh(__fdividef(c_, n_));

        hn[my_row * HH + my_hid] = hv;
        out[((long long)(b0 + my_row) * SS + step) * HH + my_hid] = hv;

        p0 = q0; p1 = q1;
        __syncthreads();
    }
}

extern "C" void kernel_launch(void* const* d_in, const int* in_sizes, int n_in,
                              void* d_out, int out_size)
{
    const float* xg = (const float*)d_in[0];
    const float* Wm = (const float*)d_in[1];
    const float* Rm = (const float*)d_in[2];
    const float* bv = (const float*)d_in[3];
    if (n_in >= 3 && in_sizes[1] == HH * GG && in_sizes[2] == GG * II) {
        const float* t = Wm; Wm = Rm; Rm = t;
    }
    float* out = (float*)d_out;

    float* pre = nullptr;
    cudaGetSymbolAddress((void**)&pre, g_pre);

    cudaFuncSetAttribute(pre_gemm_prologue,
                         cudaFuncAttributeMaxDynamicSharedMemorySize, SMEM_BYTES);
    cudaFuncSetAttribute(slstm_combined_kernel,
                         cudaFuncAttributeMaxDynamicSharedMemorySize, SMEM_BYTES);

    prep_w_kernel<<<64, 256>>>(Wm);
    pre_gemm_prologue<<<BB * PRE_TPB, NTHR, SMEM_BYTES>>>(xg, pre);
    slstm_combined_kernel<<<NPROD + NSCAN, NTHR, SMEM_BYTES>>>(xg, Rm, bv, pre, out);
}

// round 15
// speedup vs baseline: 1.2290x; 1.2290x over previous
#include <cuda_runtime.h>
#include <cuda_bf16.h>
#include <cstdint>

// Round 15: serial two-phase (max clock per phase), both phases optimized.
//   Phase 1: persistent HMMA GEMM (148 CTAs, B-tile loaded ONCE per CTA,
//            next-A prefetched into regs under current HMMA) -> pre = x@W^T.
//   Phase 2: round-7 scan, unchanged (FFMA2 mainloop, shuffle epilogue,
//            1 barrier/step), __ldg on pre restored.

#define BB 256
#define SS 2048
#define II 64
#define HH 128
#define GG 512
#define NCTA 128
#define NTHR 256
#define NTILES ((BB * SS) / 64)         // 8192 m-rows/64 ... = 8192? no: BB*SS=524288/64 = 8192
#define GEMM_CTAS 148

#define REG_K 96
#define SMK   32
#define PTS  (SMK * 2 + 4)              // 68 floats (proven conflict-free)
#define SW_FLOATS (NTHR * PTS)
#define HB_FLOATS (2 * 2 * HH)
#define SCAN_SMEM_BYTES ((SW_FLOATS + HB_FLOATS) * 4)

#define ARS 36
#define OFF_AH 0
#define OFF_AL (64 * ARS)
#define OFF_BH (2 * 64 * ARS)
#define OFF_BL (OFF_BH + 512 * ARS)
#define PROD_UINTS (OFF_BL + 512 * ARS)
#define GEMM_SMEM_BYTES (PROD_UINTS * 4)

typedef unsigned long long u64;

__device__ float g_pre[(long long)BB * SS * GG];          // 1 GB scratch
__device__ __align__(16) unsigned g_wh[GG * II / 2];
__device__ __align__(16) unsigned g_wl[GG * II / 2];

__device__ __forceinline__ u64 ffma2(u64 a, u64 b, u64 c) {
    u64 d;
    asm("fma.rn.f32x2 %0, %1, %2, %3;" : "=l"(d) : "l"(a), "l"(b), "l"(c));
    return d;
}
__device__ __forceinline__ u64 packf2(float lo, float hi) {
    u64 r;
    asm("mov.b64 %0, {%1, %2};" : "=l"(r) : "f"(lo), "f"(hi));
    return r;
}
__device__ __forceinline__ float2 unpackf2(u64 v) {
    float2 r;
    asm("mov.b64 {%0, %1}, %2;" : "=f"(r.x), "=f"(r.y) : "l"(v));
    return r;
}
__device__ __forceinline__ float fast_tanh(float x) {
    float xc = fminf(fmaxf(x, -12.0f), 12.0f);
    float e  = __expf(2.0f * xc);
    return __fdividef(e - 1.0f, e + 1.0f);
}
__device__ __forceinline__ unsigned pack_bf16_hi(float a, float b) {
    __nv_bfloat16 ah = __float2bfloat16(a), bh = __float2bfloat16(b);
    return (unsigned)__bfloat16_as_ushort(ah) | ((unsigned)__bfloat16_as_ushort(bh) << 16);
}
__device__ __forceinline__ unsigned pack_bf16_lo(float a, float b) {
    __nv_bfloat16 ah = __float2bfloat16(a), bh = __float2bfloat16(b);
    __nv_bfloat16 al = __float2bfloat16(a - __bfloat162float(ah));
    __nv_bfloat16 bl = __float2bfloat16(b - __bfloat162float(bh));
    return (unsigned)__bfloat16_as_ushort(al) | ((unsigned)__bfloat16_as_ushort(bl) << 16);
}
__device__ __forceinline__ void mma16816(float* c, const unsigned* a,
                                         unsigned b0, unsigned b1) {
    asm volatile(
        "mma.sync.aligned.m16n8k16.row.col.f32.bf16.bf16.f32 "
        "{%0,%1,%2,%3}, {%4,%5,%6,%7}, {%8,%9}, {%0,%1,%2,%3};"
        : "+f"(c[0]), "+f"(c[1]), "+f"(c[2]), "+f"(c[3])
        : "r"(a[0]), "r"(a[1]), "r"(a[2]), "r"(a[3]), "r"(b0), "r"(b1));
}

__global__ void prep_w_kernel(const float* __restrict__ Wm) {
    int i = blockIdx.x * 256 + threadIdx.x;       // 16384 pairs
    float a = Wm[2 * i], b = Wm[2 * i + 1];
    g_wh[i] = pack_bf16_hi(a, b);
    g_wl[i] = pack_bf16_lo(a, b);
}

// ---------------------------------------------------------------------------
// Persistent GEMM: 148 CTAs; B resident; tile loop with reg-prefetched A.
// tile t -> m rows [t*64, t*64+64) of flattened (b*SS + s); N=512; K=64.
// ---------------------------------------------------------------------------
#define TOT_TILES ((BB * SS) / 64)      // 8192

__global__ void __launch_bounds__(NTHR, 1)
pre_gemm_persist(const float* __restrict__ xg, float* __restrict__ pre)
{
    extern __shared__ unsigned usm[];
    unsigned* Ah = usm + OFF_AH;
    unsigned* Al = usm + OFF_AL;
    unsigned* Bh = usm + OFF_BH;
    unsigned* Bl = usm + OFF_BL;
    const int tid = threadIdx.x;

    // ---- load B once ----
#pragma unroll
    for (int j = 0; j < 16; j++) {
        int idx = tid + j * 256;
        int n = idx >> 3, kq = idx & 7;
        uint4 hv = ((const uint4*)g_wh)[idx];
        uint4 lv = ((const uint4*)g_wl)[idx];
        *(uint4*)(Bh + n * ARS + kq * 4) = hv;
        *(uint4*)(Bl + n * ARS + kq * 4) = lv;
    }

    const int w    = tid >> 5;
    const int lane = tid & 31;
    const int gid  = lane >> 2;
    const int tig  = lane & 3;
    const int mg   = w >> 2;
    const int ng   = w & 3;

    // A prefetch regs: 8 float2 per thread (row = idx>>5, kpair = idx&31)
    float2 areg[8];
    long long tile = blockIdx.x;
    {
        const float* xt = xg + tile * 64 * II;
#pragma unroll
        for (int j = 0; j < 8; j++) {
            int idx = tid + j * 256;
            areg[j] = __ldg((const float2*)(xt + (idx >> 5) * II + (idx & 31) * 2));
        }
    }

#pragma unroll 1
    for (; tile < TOT_TILES; tile += GEMM_CTAS) {
        __syncthreads();                 // prior HMMA done reading A smem
        // store prefetched A (convert to bf16 hi/lo)
#pragma unroll
        for (int j = 0; j < 8; j++) {
            int idx = tid + j * 256;
            int row = idx >> 5, kp = idx & 31;
            Ah[row * ARS + kp] = pack_bf16_hi(areg[j].x, areg[j].y);
            Al[row * ARS + kp] = pack_bf16_lo(areg[j].x, areg[j].y);
        }
        __syncthreads();

        // prefetch next tile's A while HMMA runs
        long long nxt = tile + GEMM_CTAS;
        if (nxt < TOT_TILES) {
            const float* xt = xg + nxt * 64 * II;
#pragma unroll
            for (int j = 0; j < 8; j++) {
                int idx = tid + j * 256;
                areg[j] = __ldg((const float2*)(xt + (idx >> 5) * II + (idx & 31) * 2));
            }
        }

        float acc[2][16][4];
#pragma unroll
        for (int mt = 0; mt < 2; mt++)
#pragma unroll
            for (int nc = 0; nc < 16; nc++)
#pragma unroll
                for (int e = 0; e < 4; e++) acc[mt][nc][e] = 0.0f;

#pragma unroll
        for (int ks = 0; ks < 4; ks++) {
            unsigned ah[2][4], al[2][4];
#pragma unroll
            for (int mt = 0; mt < 2; mt++) {
                int r0 = mg * 32 + mt * 16 + gid;
                int ui = ks * 8 + tig;
                ah[mt][0] = Ah[r0 * ARS + ui];
                ah[mt][1] = Ah[(r0 + 8) * ARS + ui];
                ah[mt][2] = Ah[r0 * ARS + ui + 4];
                ah[mt][3] = Ah[(r0 + 8) * ARS + ui + 4];
                al[mt][0] = Al[r0 * ARS + ui];
                al[mt][1] = Al[(r0 + 8) * ARS + ui];
                al[mt][2] = Al[r0 * ARS + ui + 4];
                al[mt][3] = Al[(r0 + 8) * ARS + ui + 4];
            }
#pragma unroll
            for (int nc = 0; nc < 16; nc++) {
                int n  = ng * 128 + nc * 8 + gid;
                int ui = ks * 8 + tig;
                unsigned bh0 = Bh[n * ARS + ui];
                unsigned bh1 = Bh[n * ARS + ui + 4];
                unsigned bl0 = Bl[n * ARS + ui];
                unsigned bl1 = Bl[n * ARS + ui + 4];
#pragma unroll
                for (int mt = 0; mt < 2; mt++) {
                    mma16816(acc[mt][nc], ah[mt], bh0, bh1);
                    mma16816(acc[mt][nc], al[mt], bh0, bh1);
                    mma16816(acc[mt][nc], ah[mt], bl0, bl1);
                }
            }
        }
        long long mbase = tile * 64;
#pragma unroll
        for (int mt = 0; mt < 2; mt++) {
#pragma unroll
            for (int nc = 0; nc < 16; nc++) {
                long long m = mbase + mg * 32 + mt * 16 + gid;
                int n = ng * 128 + nc * 8 + tig * 2;
                *(float2*)(pre + m * GG + n)       = make_float2(acc[mt][nc][0], acc[mt][nc][1]);
                *(float2*)(pre + (m + 8) * GG + n) = make_float2(acc[mt][nc][2], acc[mt][nc][3]);
            }
        }
    }
}

// ---------------------------------------------------------------------------
// scan: round-7 body (REG_K=96 reg rows + SMK=32 smem rows, FFMA2 mainloop,
// shuffle epilogue, 1 barrier/step). __ldg on pre (written by prior kernel).
// ---------------------------------------------------------------------------
__global__ void __launch_bounds__(NTHR, 1)
slstm_scan_kernel(const float* __restrict__ pre, const float* __restrict__ Rm,
                  const float* __restrict__ bias, float* __restrict__ out)
{
    extern __shared__ float smem[];
    float* sW = smem;                    // [256][PTS]
    float* hb = smem + SW_FLOATS;        // [2][2][HH]

    const int tid = threadIdx.x;
    const int w   = tid >> 5;
    const int l   = tid & 31;
    const int c0  = 16 * l + 2 * w;
    const int c1  = c0 + 1;
    const int b0  = blockIdx.x * 2;

    u64 wp0[REG_K / 2], wp1[REG_K / 2];
#pragma unroll
    for (int j = 0; j < REG_K / 2; j++) {
        wp0[j] = packf2(Rm[(2 * j) * GG + c0], Rm[(2 * j + 1) * GG + c0]);
        wp1[j] = packf2(Rm[(2 * j) * GG + c1], Rm[(2 * j + 1) * GG + c1]);
    }
    {
        float* slab = sW + tid * PTS;
#pragma unroll
        for (int kc = 0; kc < SMK; kc += 4) {
            int k = REG_K + kc;
            slab[kc * 2 + 0] = Rm[(k + 0) * GG + c0];
            slab[kc * 2 + 1] = Rm[(k + 1) * GG + c0];
            slab[kc * 2 + 2] = Rm[(k + 0) * GG + c1];
            slab[kc * 2 + 3] = Rm[(k + 1) * GG + c1];
            slab[kc * 2 + 4] = Rm[(k + 2) * GG + c0];
            slab[kc * 2 + 5] = Rm[(k + 3) * GG + c0];
            slab[kc * 2 + 6] = Rm[(k + 2) * GG + c1];
            slab[kc * 2 + 7] = Rm[(k + 3) * GG + c1];
        }
    }
    const float bg0 = bias[c0];
    const float bg1 = bias[c1];

    hb[tid] = 0.0f;
    hb[tid + 256] = 0.0f;
    __syncthreads();

    const float* pr0 = pre + (long long)(b0)     * SS * GG;
    const float* pr1 = pre + (long long)(b0 + 1) * SS * GG;

    float2 p0 = __ldg((const float2*)(pr0 + c0));
    float2 p1 = __ldg((const float2*)(pr1 + c0));

    const int my_row = (l >> 4) & 1;
    const int my_hid = 16 * (l & 7) + 2 * w + ((l >> 3) & 1);
    float c_ = 0.0f, n_ = 0.0f, m_ = 0.0f;

    const bool lo16 = (l < 16);
    const bool b3   = ((l >> 3) & 1) != 0;
    const float* sWg = sW + tid * PTS;

    // strength-reduced output pointer for this lane's (row, hid)
    float* outp = out + ((long long)(b0 + my_row) * SS) * HH + my_hid;

#pragma unroll 1
    for (int step = 0; step < SS; step++) {
        const float* h0 = hb + (step & 1) * 256;
        const float* h1 = h0 + HH;
        float* hn = hb + ((step + 1) & 1) * 256;

        float2 q0 = make_float2(0.f, 0.f), q1 = make_float2(0.f, 0.f);
        if (step + 1 < SS) {
            long long off = (long long)(step + 1) * GG;
            q0 = __ldg((const float2*)(pr0 + off + c0));
            q1 = __ldg((const float2*)(pr1 + off + c0));
        }

        u64 a00 = 0, a10 = 0, a01 = 0, a11 = 0;

#pragma unroll
        for (int k = 0; k < REG_K; k += 4) {
            ulonglong2 hp0 = *(const ulonglong2*)(h0 + k);
            ulonglong2 hp1 = *(const ulonglong2*)(h1 + k);
            int j = k / 2;
            a00 = ffma2(hp0.x, wp0[j],     a00);
            a10 = ffma2(hp0.x, wp1[j],     a10);
            a01 = ffma2(hp1.x, wp0[j],     a01);
            a11 = ffma2(hp1.x, wp1[j],     a11);
            a00 = ffma2(hp0.y, wp0[j + 1], a00);
            a10 = ffma2(hp0.y, wp1[j + 1], a10);
            a01 = ffma2(hp1.y, wp0[j + 1], a01);
            a11 = ffma2(hp1.y, wp1[j + 1], a11);
        }
#pragma unroll
        for (int k = 0; k < SMK; k += 4) {
            ulonglong2 wv0 = *(const ulonglong2*)(sWg + k * 2);
            ulonglong2 wv1 = *(const ulonglong2*)(sWg + k * 2 + 4);
            ulonglong2 hp0 = *(const ulonglong2*)(h0 + REG_K + k);
            ulonglong2 hp1 = *(const ulonglong2*)(h1 + REG_K + k);
            a00 = ffma2(hp0.x, wv0.x, a00);
            a10 = ffma2(hp0.x, wv0.y, a10);
            a01 = ffma2(hp1.x, wv0.x, a01);
            a11 = ffma2(hp1.x, wv0.y, a11);
            a00 = ffma2(hp0.y, wv1.x, a00);
            a10 = ffma2(hp0.y, wv1.y, a10);
            a01 = ffma2(hp1.y, wv1.x, a01);
            a11 = ffma2(hp1.y, wv1.y, a11);
        }

        float2 t0 = unpackf2(a00), t1 = unpackf2(a10);
        float2 t2 = unpackf2(a01), t3 = unpackf2(a11);
        float aa = t0.x + t0.y + p0.x + bg0;
        float bb = t1.x + t1.y + p0.y + bg1;
        float cc = t2.x + t2.y + p1.x + bg0;
        float dd = t3.x + t3.y + p1.y + bg1;

        // warp-local gate transpose (4 shuffles)
        float u1 = lo16 ? cc : aa;
        float u2 = lo16 ? dd : bb;
        float r1v = __shfl_xor_sync(0xFFFFFFFFu, u1, 16);
        float r2v = __shfl_xor_sync(0xFFFFFFFFu, u2, 16);
        float Ag = lo16 ? aa : r1v;
        float Bg = lo16 ? bb : r2v;
        float Cg = lo16 ? r1v : cc;
        float Dg = lo16 ? r2v : dd;
        float s1in = b3 ? Ag : Bg;
        float s2in = b3 ? Cg : Dg;
        float e1 = __shfl_xor_sync(0xFFFFFFFFu, s1in, 8);
        float e2 = __shfl_xor_sync(0xFFFFFFFFu, s2in, 8);
        float iv = b3 ? e1 : Ag;
        float fv = b3 ? Bg : e1;
        float ov = b3 ? e2 : Cg;
        float zv = b3 ? Dg : e2;

        float tz = fast_tanh(zv);
        float so = __fdividef(1.0f, 1.0f + __expf(-ov));
        float lf = fminf(fv, 0.0f) - __logf(1.0f + __expf(-fabsf(fv)));
        float mn = fmaxf(lf + m_, iv);
        float ip = __expf(iv - mn);
        float fp = __expf(lf + m_ - mn);
        c_ = fp * c_ + ip * tz;
        n_ = fp * n_ + ip;
        m_ = mn;
        float hv = so * fast_tanh(__fdividef(c_, n_));

        hn[my_row * HH + my_hid] = hv;
        outp[0] = hv;
        outp += HH;

        p0 = q0; p1 = q1;
        __syncthreads();
    }
}

extern "C" void kernel_launch(void* const* d_in, const int* in_sizes, int n_in,
                              void* d_out, int out_size)
{
    const float* xg = (const float*)d_in[0];
    const float* Wm = (const float*)d_in[1];
    const float* Rm = (const float*)d_in[2];
    const float* bv = (const float*)d_in[3];
    if (n_in >= 3 && in_sizes[1] == HH * GG && in_sizes[2] == GG * II) {
        const float* t = Wm; Wm = Rm; Rm = t;
    }
    float* out = (float*)d_out;

    float* pre = nullptr;
    cudaGetSymbolAddress((void**)&pre, g_pre);

    cudaFuncSetAttribute(pre_gemm_persist,
                         cudaFuncAttributeMaxDynamicSharedMemorySize, GEMM_SMEM_BYTES);
    cudaFuncSetAttribute(slstm_scan_kernel,
                         cudaFuncAttributeMaxDynamicSharedMemorySize, SCAN_SMEM_BYTES);

    prep_w_kernel<<<64, 256>>>(Wm);
    pre_gemm_persist<<<GEMM_CTAS, NTHR, GEMM_SMEM_BYTES>>>(xg, pre);
    slstm_scan_kernel<<<NCTA, NTHR, SCAN_SMEM_BYTES>>>(pre, Rm, bv, out);
}